// round 14
// baseline (speedup 1.0000x reference)
#include <cuda_runtime.h>
#include <cuda_fp16.h>

// Problem constants
#define CAP_A   32
#define CAP_B   32
#define KK      3
#define PSIZE   16
#define STRIDE  2
#define OH      15
#define OW      15
#define NBATCH  2
#define NPOS    (NBATCH*OH*OW)   // 450
#define KKA     (KK*KK*CAP_A)    // 288
#define NX      (NBATCH*32*32*512)  // 1,048,576 x elements
#define EPS_SQ  1e-8f
#define CPT     9                // capsules per thread (one warp per (n,j))
#define FULL    0xffffffffu
#define W4      (KKA*CAP_B*4)    // 36864 float4s in w
#define X4      (NX/4)           // 262144 float4s in x

// fp16 staging buffers (device globals; prep kernel fills them in-graph)
__device__ __half w_h[CAP_B * KKA * PSIZE];   // transposed: [j][i][16]
__device__ __half x_h[NX];                    // same layout as x

// Single prep kernel: converts w (with j-major transpose) and x to fp16.
__global__ void convert_kernel(const float* __restrict__ w,
                               const float* __restrict__ x) {
    const int f = blockIdx.x * blockDim.x + threadIdx.x;
    if (f < W4) {
        const int q4 = f & 3;
        const int j  = (f >> 2) & 31;
        const int i  = f >> 7;
        const float4 val = reinterpret_cast<const float4*>(w)[f];
        __half2* dst = reinterpret_cast<__half2*>(w_h + (j * KKA + i) * PSIZE + q4 * 4);
        dst[0] = __floats2half2_rn(val.x, val.y);
        dst[1] = __floats2half2_rn(val.z, val.w);
    } else {
        const int g = f - W4;
        if (g < X4) {
            const float4 val = reinterpret_cast<const float4*>(x)[g];
            __half2* dst = reinterpret_cast<__half2*>(x_h + g * 4);
            dst[0] = __floats2half2_rn(val.x, val.y);
            dst[1] = __floats2half2_rn(val.z, val.w);
        }
    }
}

// Load 16 contiguous halves (32B), widen to fp32 scalars.
__device__ __forceinline__ void load16h(const __half* __restrict__ p, float o[16]) {
    uint4 u0 = *reinterpret_cast<const uint4*>(p);
    uint4 u1 = *reinterpret_cast<const uint4*>(p + 8);
    const unsigned wds[8] = {u0.x, u0.y, u0.z, u0.w, u1.x, u1.y, u1.z, u1.w};
#pragma unroll
    for (int k = 0; k < 8; k++) {
        const float2 f2 = __half22float2(*reinterpret_cast<const __half2*>(&wds[k]));
        o[2 * k]     = f2.x;
        o[2 * k + 1] = f2.y;
    }
}

// Butterfly vector-exchange reduction: 32 lanes each hold t[0..15];
// afterwards lane l holds the lane-sum of component (l & 15). 31 shuffles.
__device__ __forceinline__ void vec_reduce16(float t[16], int lane) {
#pragma unroll
    for (int k = 0; k < 16; k++)
        t[k] += __shfl_xor_sync(FULL, t[k], 16);
    {
        const bool hi = lane & 8;
#pragma unroll
        for (int k = 0; k < 8; k++) {
            float keep = hi ? t[k + 8] : t[k];
            float send = hi ? t[k]     : t[k + 8];
            t[k] = keep + __shfl_xor_sync(FULL, send, 8);
        }
    }
    {
        const bool hi = lane & 4;
#pragma unroll
        for (int k = 0; k < 4; k++) {
            float keep = hi ? t[k + 4] : t[k];
            float send = hi ? t[k]     : t[k + 4];
            t[k] = keep + __shfl_xor_sync(FULL, send, 4);
        }
    }
    {
        const bool hi = lane & 2;
#pragma unroll
        for (int k = 0; k < 2; k++) {
            float keep = hi ? t[k + 2] : t[k];
            float send = hi ? t[k]     : t[k + 2];
            t[k] = keep + __shfl_xor_sync(FULL, send, 2);
        }
    }
    {
        const bool hi = lane & 1;
        float keep = hi ? t[1] : t[0];
        float send = hi ? t[0] : t[1];
        t[0] = keep + __shfl_xor_sync(FULL, send, 1);
    }
}

// Squash on the duplicated 16-vector (lanes l and l+16 both hold comp l&15).
__device__ __forceinline__ float squash16(float s) {
    float n2 = s * s;
#pragma unroll
    for (int off = 8; off >= 1; off >>= 1)
        n2 += __shfl_xor_sync(FULL, n2, off);
    return s * (n2 / (1.f + n2) * rsqrtf(n2 + EPS_SQ));
}

__global__ __launch_bounds__(32, 14) void caps_warp_kernel(
    float* __restrict__ out)         // (2, 15, 15, 512)
{
    const int bid = blockIdx.x;
    const int j   = bid & 31;
    const int n   = bid >> 5;
    const int b   = n / (OH * OW);
    const int rem = n % (OH * OW);
    const int oy  = rem / OW;
    const int ox  = rem % OW;

    const int lane = threadIdx.x;    // = a (input capsule type)

    // Thread owns i_c = c*32 + lane, c = ky*3 + kx.
    const __half* xbase = x_h + ((size_t)((b * 32 + oy * STRIDE) * 32
                                          + ox * STRIDE) * 512 + lane * PSIZE);
    const __half* wbase = w_h + ((size_t)j * KKA + lane) * PSIZE;   // coalesced

    // v stored packed as half2 (halves register footprint -> more warps/SM).
    __half2 v_h2[CPT][8];
    float t[16];                     // iter-0 pool accumulated fp32, pre-rounding
#pragma unroll
    for (int q = 0; q < 16; q++) t[q] = 0.f;

#pragma unroll
    for (int c = 0; c < CPT; c++) {
        const int ky = c / 3, kx = c % 3;
        float xm[16], wm[16];
        load16h(xbase + (size_t)(ky * 32 + kx) * 512, xm);
        load16h(wbase + (size_t)(c * 32) * PSIZE,     wm);
        float vv[16];
#pragma unroll
        for (int p = 0; p < 4; p++)
#pragma unroll
            for (int q = 0; q < 4; q++) {
                float acc = 0.f;
#pragma unroll
                for (int r = 0; r < 4; r++)
                    acc = fmaf(xm[p * 4 + r], wm[r * 4 + q], acc);
                vv[p * 4 + q] = acc;
                t[p * 4 + q] += acc;     // iter-0 pool, exact
            }
#pragma unroll
        for (int k = 0; k < 8; k++)
            v_h2[c][k] = __floats2half2_rn(vv[2 * k], vv[2 * k + 1]);
    }

    float logit[CPT];
#pragma unroll
    for (int c = 0; c < CPT; c++) logit[c] = 0.f;

    float pval;   // component (lane&15) of current p

    // ---- iteration 0: logits all zero -> r = 1/288 exactly ----
    vec_reduce16(t, lane);
    pval = squash16(t[0] * (1.0f / (float)KKA));

    // agreement: logit_c += v_c . p
#pragma unroll
    for (int k = 0; k < 8; k++) {
        const float px = __shfl_sync(FULL, pval, 2 * k);
        const float py = __shfl_sync(FULL, pval, 2 * k + 1);
#pragma unroll
        for (int c = 0; c < CPT; c++) {
            const float2 f = __half22float2(v_h2[c][k]);
            logit[c] = fmaf(f.x, px, fmaf(f.y, py, logit[c]));
        }
    }

    // ---- iterations 1..2 ----
    // Logits are bounded (|logit| <~ 20), so softmax without max-subtraction
    // is safe in fp32 and mathematically identical.
#pragma unroll
    for (int it = 1; it < 3; it++) {
        float e[CPT], z = 0.f;
#pragma unroll
        for (int c = 0; c < CPT; c++) { e[c] = __expf(logit[c]); z += e[c]; }
#pragma unroll
        for (int off = 16; off >= 1; off >>= 1)
            z += __shfl_xor_sync(FULL, z, off);
        const float rZ = __frcp_rn(z);

        // pool with weights e_c (fp32 accumulate), scale by 1/Z afterwards
#pragma unroll
        for (int k = 0; k < 8; k++) {
            float ax = 0.f, ay = 0.f;
#pragma unroll
            for (int c = 0; c < CPT; c++) {
                const float2 f = __half22float2(v_h2[c][k]);
                ax = fmaf(e[c], f.x, ax);
                ay = fmaf(e[c], f.y, ay);
            }
            t[2 * k]     = ax;
            t[2 * k + 1] = ay;
        }
        vec_reduce16(t, lane);
        pval = squash16(t[0] * rZ);

        if (it < 2) {
#pragma unroll
            for (int k = 0; k < 8; k++) {
                const float px = __shfl_sync(FULL, pval, 2 * k);
                const float py = __shfl_sync(FULL, pval, 2 * k + 1);
#pragma unroll
                for (int c = 0; c < CPT; c++) {
                    const float2 f = __half22float2(v_h2[c][k]);
                    logit[c] = fmaf(f.x, px, fmaf(f.y, py, logit[c]));
                }
            }
        }
    }

    // ---- output: lanes 0..15 hold p[0..15] ----
    if (lane < 16)
        out[(size_t)n * (CAP_B * PSIZE) + j * PSIZE + lane] = pval;
}

extern "C" void kernel_launch(void* const* d_in, const int* in_sizes, int n_in,
                              void* d_out, int out_size) {
    (void)in_sizes; (void)n_in; (void)out_size;
    const float* x = (const float*)d_in[0];
    const float* w = (const float*)d_in[1];
    float* out = (float*)d_out;

    // 1) single prep launch: fp32 -> fp16 (w transposed to j-major) + x
    convert_kernel<<<(W4 + X4 + 255) / 256, 256>>>(w, x);

    // 2) fused transform + routing, one warp per (n, j)
    dim3 grid(NPOS * CAP_B);   // 14400
    caps_warp_kernel<<<grid, 32>>>(out);
}

// round 15
// speedup vs baseline: 1.1315x; 1.1315x over previous
#include <cuda_runtime.h>
#include <cuda_fp16.h>

// Problem constants
#define CAP_A   32
#define CAP_B   32
#define KK      3
#define PSIZE   16
#define STRIDE  2
#define OH      15
#define OW      15
#define NBATCH  2
#define NPOS    (NBATCH*OH*OW)   // 450
#define KKA     (KK*KK*CAP_A)    // 288
#define NX      (NBATCH*32*32*512)  // 1,048,576 x elements
#define EPS_SQ  1e-8f
#define CPT     9                // capsules per thread (one warp per (n,j))
#define JPW     4                // j values per warp (sequential, x reused in L1)
#define FULL    0xffffffffu
#define W4      (KKA*CAP_B*4)    // 36864 float4s in w
#define X4      (NX/4)           // 262144 float4s in x

// fp16 staging buffers (device globals; prep kernel fills them in-graph)
__device__ __half w_h[CAP_B * KKA * PSIZE];   // transposed: [j][i][16]
__device__ __half x_h[NX];                    // same layout as x

// Single prep kernel: converts w (with j-major transpose) and x to fp16.
__global__ void convert_kernel(const float* __restrict__ w,
                               const float* __restrict__ x) {
    const int f = blockIdx.x * blockDim.x + threadIdx.x;
    if (f < W4) {
        const int q4 = f & 3;
        const int j  = (f >> 2) & 31;
        const int i  = f >> 7;
        const float4 val = reinterpret_cast<const float4*>(w)[f];
        __half2* dst = reinterpret_cast<__half2*>(w_h + (j * KKA + i) * PSIZE + q4 * 4);
        dst[0] = __floats2half2_rn(val.x, val.y);
        dst[1] = __floats2half2_rn(val.z, val.w);
    } else {
        const int g = f - W4;
        if (g < X4) {
            const float4 val = reinterpret_cast<const float4*>(x)[g];
            __half2* dst = reinterpret_cast<__half2*>(x_h + g * 4);
            dst[0] = __floats2half2_rn(val.x, val.y);
            dst[1] = __floats2half2_rn(val.z, val.w);
        }
    }
}

// Load 16 contiguous halves (32B), widen to fp32 scalars.
__device__ __forceinline__ void load16h(const __half* __restrict__ p, float o[16]) {
    uint4 u0 = *reinterpret_cast<const uint4*>(p);
    uint4 u1 = *reinterpret_cast<const uint4*>(p + 8);
    const unsigned wds[8] = {u0.x, u0.y, u0.z, u0.w, u1.x, u1.y, u1.z, u1.w};
#pragma unroll
    for (int k = 0; k < 8; k++) {
        const float2 f2 = __half22float2(*reinterpret_cast<const __half2*>(&wds[k]));
        o[2 * k]     = f2.x;
        o[2 * k + 1] = f2.y;
    }
}

// Butterfly vector-exchange reduction: 32 lanes each hold t[0..15];
// afterwards lane l holds the lane-sum of component (l & 15). 31 shuffles.
__device__ __forceinline__ void vec_reduce16(float t[16], int lane) {
#pragma unroll
    for (int k = 0; k < 16; k++)
        t[k] += __shfl_xor_sync(FULL, t[k], 16);
    {
        const bool hi = lane & 8;
#pragma unroll
        for (int k = 0; k < 8; k++) {
            float keep = hi ? t[k + 8] : t[k];
            float send = hi ? t[k]     : t[k + 8];
            t[k] = keep + __shfl_xor_sync(FULL, send, 8);
        }
    }
    {
        const bool hi = lane & 4;
#pragma unroll
        for (int k = 0; k < 4; k++) {
            float keep = hi ? t[k + 4] : t[k];
            float send = hi ? t[k]     : t[k + 4];
            t[k] = keep + __shfl_xor_sync(FULL, send, 4);
        }
    }
    {
        const bool hi = lane & 2;
#pragma unroll
        for (int k = 0; k < 2; k++) {
            float keep = hi ? t[k + 2] : t[k];
            float send = hi ? t[k]     : t[k + 2];
            t[k] = keep + __shfl_xor_sync(FULL, send, 2);
        }
    }
    {
        const bool hi = lane & 1;
        float keep = hi ? t[1] : t[0];
        float send = hi ? t[0] : t[1];
        t[0] = keep + __shfl_xor_sync(FULL, send, 1);
    }
}

// Squash on the duplicated 16-vector (lanes l and l+16 both hold comp l&15).
__device__ __forceinline__ float squash16(float s) {
    float n2 = s * s;
#pragma unroll
    for (int off = 8; off >= 1; off >>= 1)
        n2 += __shfl_xor_sync(FULL, n2, off);
    return s * (n2 / (1.f + n2) * rsqrtf(n2 + EPS_SQ));
}

// One full (n,j) unit: matmul + 3 routing iterations + output store.
__device__ __forceinline__ void caps_unit(
    const __half* __restrict__ xbase,   // x patch base for (n, lane)
    const __half* __restrict__ wbase,   // w_t base for (j, lane)
    float* __restrict__ outp,           // out + n*512 + j*16
    int lane)
{
    float v[CPT][16];
#pragma unroll
    for (int c = 0; c < CPT; c++) {
        const int ky = c / 3, kx = c % 3;
        float xm[16], wm[16];
        load16h(xbase + (size_t)(ky * 32 + kx) * 512, xm);
        load16h(wbase + (size_t)(c * 32) * PSIZE,     wm);
#pragma unroll
        for (int p = 0; p < 4; p++)
#pragma unroll
            for (int q = 0; q < 4; q++) {
                float acc = 0.f;
#pragma unroll
                for (int r = 0; r < 4; r++)
                    acc = fmaf(xm[p * 4 + r], wm[r * 4 + q], acc);
                v[c][p * 4 + q] = acc;
            }
    }

    float logit[CPT];
#pragma unroll
    for (int c = 0; c < CPT; c++) logit[c] = 0.f;

    float t[16];
    float pval;   // component (lane&15) of current p

    // ---- iteration 0: logits all zero -> r = 1/288 exactly ----
#pragma unroll
    for (int q = 0; q < 16; q++) {
        float s = v[0][q];
#pragma unroll
        for (int c = 1; c < CPT; c++) s += v[c][q];
        t[q] = s;
    }
    vec_reduce16(t, lane);
    pval = squash16(t[0] * (1.0f / (float)KKA));

    // agreement: logit_c += v_c . p  (p broadcast via inline shuffles)
#pragma unroll
    for (int q = 0; q < 16; q++) {
        const float pq = __shfl_sync(FULL, pval, q);
#pragma unroll
        for (int c = 0; c < CPT; c++)
            logit[c] = fmaf(v[c][q], pq, logit[c]);
    }

    // ---- iterations 1..2 ----
    // Logits are bounded (|logit| <~ 20), so softmax without max-subtraction
    // is safe in fp32 and mathematically identical.
#pragma unroll
    for (int it = 1; it < 3; it++) {
        float e[CPT], z = 0.f;
#pragma unroll
        for (int c = 0; c < CPT; c++) { e[c] = __expf(logit[c]); z += e[c]; }
#pragma unroll
        for (int off = 16; off >= 1; off >>= 1)
            z += __shfl_xor_sync(FULL, z, off);
        const float rZ = __frcp_rn(z);

        // pool with weights e_c (scale by 1/Z after the reduction)
#pragma unroll
        for (int q = 0; q < 16; q++) {
            float s = e[0] * v[0][q];
#pragma unroll
            for (int c = 1; c < CPT; c++) s = fmaf(e[c], v[c][q], s);
            t[q] = s;
        }
        vec_reduce16(t, lane);
        pval = squash16(t[0] * rZ);

        if (it < 2) {
#pragma unroll
            for (int q = 0; q < 16; q++) {
                const float pq = __shfl_sync(FULL, pval, q);
#pragma unroll
                for (int c = 0; c < CPT; c++)
                    logit[c] = fmaf(v[c][q], pq, logit[c]);
            }
        }
    }

    // ---- output: lanes 0..15 hold p[0..15] ----
    if (lane < 16)
        outp[lane] = pval;
}

__global__ __launch_bounds__(32, 10) void caps_warp_kernel(
    float* __restrict__ out)         // (2, 15, 15, 512)
{
    const int bid = blockIdx.x;
    const int jg  = bid & 7;               // j group (4 j's each)
    const int n   = bid >> 3;              // position index
    const int b   = n / (OH * OW);
    const int rem = n % (OH * OW);
    const int oy  = rem / OW;
    const int ox  = rem % OW;

    const int lane = threadIdx.x;    // = a (input capsule type)

    // x patch base (shared by all 4 j's; stays L1-resident across iterations)
    const __half* xbase = x_h + ((size_t)((b * 32 + oy * STRIDE) * 32
                                          + ox * STRIDE) * 512 + lane * PSIZE);
    float* outn = out + (size_t)n * (CAP_B * PSIZE);

#pragma unroll 1
    for (int jj = 0; jj < JPW; jj++) {
        const int j = jg * JPW + jj;
        const __half* wbase = w_h + ((size_t)j * KKA + lane) * PSIZE;
        caps_unit(xbase, wbase, outn + j * PSIZE, lane);
    }
}

extern "C" void kernel_launch(void* const* d_in, const int* in_sizes, int n_in,
                              void* d_out, int out_size) {
    (void)in_sizes; (void)n_in; (void)out_size;
    const float* x = (const float*)d_in[0];
    const float* w = (const float*)d_in[1];
    float* out = (float*)d_out;

    // 1) single prep launch: fp32 -> fp16 (w transposed to j-major) + x
    convert_kernel<<<(W4 + X4 + 255) / 256, 256>>>(w, x);

    // 2) fused transform + routing; each warp does 4 j's of one n
    dim3 grid(NPOS * (CAP_B / JPW));   // 3600
    caps_warp_kernel<<<grid, 32>>>(out);
}

// round 16
// speedup vs baseline: 1.3592x; 1.2012x over previous
#include <cuda_runtime.h>
#include <cuda_fp16.h>

// Problem constants
#define CAP_A   32
#define CAP_B   32
#define KK      3
#define PSIZE   16
#define STRIDE  2
#define OH      15
#define OW      15
#define NBATCH  2
#define NPOS    (NBATCH*OH*OW)   // 450
#define KKA     (KK*KK*CAP_A)    // 288
#define NX      (NBATCH*32*32*512)  // 1,048,576 x elements
#define EPS_SQ  1e-8f
#define CPT     9                // capsules per thread (one warp per (n,j))
#define FULL    0xffffffffu
#define W4      (KKA*CAP_B*4)    // 36864 float4s in w
#define X4      (NX/4)           // 262144 float4s in x

// fp16 staging buffers (device globals; prep kernel fills them in-graph)
__device__ __half w_h[CAP_B * KKA * PSIZE];   // transposed: [j][i][16]
__device__ __half x_h[NX];                    // same layout as x

// Single prep kernel: converts w (with j-major transpose) and x to fp16.
__global__ void convert_kernel(const float* __restrict__ w,
                               const float* __restrict__ x) {
    const int f = blockIdx.x * blockDim.x + threadIdx.x;
    if (f < W4) {
        const int q4 = f & 3;
        const int j  = (f >> 2) & 31;
        const int i  = f >> 7;
        const float4 val = reinterpret_cast<const float4*>(w)[f];
        __half2* dst = reinterpret_cast<__half2*>(w_h + (j * KKA + i) * PSIZE + q4 * 4);
        dst[0] = __floats2half2_rn(val.x, val.y);
        dst[1] = __floats2half2_rn(val.z, val.w);
    } else {
        const int g = f - W4;
        if (g < X4) {
            const float4 val = reinterpret_cast<const float4*>(x)[g];
            __half2* dst = reinterpret_cast<__half2*>(x_h + g * 4);
            dst[0] = __floats2half2_rn(val.x, val.y);
            dst[1] = __floats2half2_rn(val.z, val.w);
        }
    }
}

// Load 16 contiguous halves (32B), widen to fp32 scalars.
__device__ __forceinline__ void load16h(const __half* __restrict__ p, float o[16]) {
    uint4 u0 = *reinterpret_cast<const uint4*>(p);
    uint4 u1 = *reinterpret_cast<const uint4*>(p + 8);
    const unsigned wds[8] = {u0.x, u0.y, u0.z, u0.w, u1.x, u1.y, u1.z, u1.w};
#pragma unroll
    for (int k = 0; k < 8; k++) {
        const float2 f2 = __half22float2(*reinterpret_cast<const __half2*>(&wds[k]));
        o[2 * k]     = f2.x;
        o[2 * k + 1] = f2.y;
    }
}

// Butterfly vector-exchange reduction: 32 lanes each hold t[0..15];
// afterwards lane l holds the lane-sum of component (l & 15). 31 shuffles.
__device__ __forceinline__ void vec_reduce16(float t[16], int lane) {
#pragma unroll
    for (int k = 0; k < 16; k++)
        t[k] += __shfl_xor_sync(FULL, t[k], 16);
    {
        const bool hi = lane & 8;
#pragma unroll
        for (int k = 0; k < 8; k++) {
            float keep = hi ? t[k + 8] : t[k];
            float send = hi ? t[k]     : t[k + 8];
            t[k] = keep + __shfl_xor_sync(FULL, send, 8);
        }
    }
    {
        const bool hi = lane & 4;
#pragma unroll
        for (int k = 0; k < 4; k++) {
            float keep = hi ? t[k + 4] : t[k];
            float send = hi ? t[k]     : t[k + 4];
            t[k] = keep + __shfl_xor_sync(FULL, send, 4);
        }
    }
    {
        const bool hi = lane & 2;
#pragma unroll
        for (int k = 0; k < 2; k++) {
            float keep = hi ? t[k + 2] : t[k];
            float send = hi ? t[k]     : t[k + 2];
            t[k] = keep + __shfl_xor_sync(FULL, send, 2);
        }
    }
    {
        const bool hi = lane & 1;
        float keep = hi ? t[1] : t[0];
        float send = hi ? t[0] : t[1];
        t[0] = keep + __shfl_xor_sync(FULL, send, 1);
    }
}

// Squash on the duplicated 16-vector (lanes l and l+16 both hold comp l&15).
__device__ __forceinline__ float squash16(float s) {
    float n2 = s * s;
#pragma unroll
    for (int off = 8; off >= 1; off >>= 1)
        n2 += __shfl_xor_sync(FULL, n2, off);
    return s * (n2 / (1.f + n2) * rsqrtf(n2 + EPS_SQ));
}

__global__ __launch_bounds__(32, 12) void caps_warp_kernel(
    float* __restrict__ out)         // (2, 15, 15, 512)
{
    const int bid = blockIdx.x;
    const int j   = bid & 31;
    const int n   = bid >> 5;
    const int b   = n / (OH * OW);
    const int rem = n % (OH * OW);
    const int oy  = rem / OW;
    const int ox  = rem % OW;

    const int lane = threadIdx.x;    // = a (input capsule type)

    // Thread owns i_c = c*32 + lane, c = ky*3 + kx.
    const __half* xbase = x_h + ((size_t)((b * 32 + oy * STRIDE) * 32
                                          + ox * STRIDE) * 512 + lane * PSIZE);
    const __half* wbase = w_h + ((size_t)j * KKA + lane) * PSIZE;   // coalesced

    float v[CPT][16];
#pragma unroll
    for (int c = 0; c < CPT; c++) {
        const int ky = c / 3, kx = c % 3;
        float xm[16], wm[16];
        load16h(xbase + (size_t)(ky * 32 + kx) * 512, xm);
        load16h(wbase + (size_t)(c * 32) * PSIZE,     wm);
#pragma unroll
        for (int p = 0; p < 4; p++)
#pragma unroll
            for (int q = 0; q < 4; q++) {
                float acc = 0.f;
#pragma unroll
                for (int r = 0; r < 4; r++)
                    acc = fmaf(xm[p * 4 + r], wm[r * 4 + q], acc);
                v[c][p * 4 + q] = acc;
            }
    }

    float logit[CPT];
#pragma unroll
    for (int c = 0; c < CPT; c++) logit[c] = 0.f;

    float t[16];
    float pval;   // component (lane&15) of current p

    // ---- iteration 0: logits all zero -> r = 1/288 exactly ----
#pragma unroll
    for (int q = 0; q < 16; q++) {
        float s = v[0][q];
#pragma unroll
        for (int c = 1; c < CPT; c++) s += v[c][q];
        t[q] = s;
    }
    vec_reduce16(t, lane);
    pval = squash16(t[0] * (1.0f / (float)KKA));

    // agreement: logit_c += v_c . p  (p broadcast via inline shuffles)
#pragma unroll
    for (int q = 0; q < 16; q++) {
        const float pq = __shfl_sync(FULL, pval, q);
#pragma unroll
        for (int c = 0; c < CPT; c++)
            logit[c] = fmaf(v[c][q], pq, logit[c]);
    }

    // ---- iterations 1..2 ----
    // Logits are bounded (|logit| <~ 20), so softmax without max-subtraction
    // is safe in fp32 and mathematically identical.
#pragma unroll
    for (int it = 1; it < 3; it++) {
        float e[CPT], z = 0.f;
#pragma unroll
        for (int c = 0; c < CPT; c++) { e[c] = __expf(logit[c]); z += e[c]; }
#pragma unroll
        for (int off = 16; off >= 1; off >>= 1)
            z += __shfl_xor_sync(FULL, z, off);
        const float rZ = __frcp_rn(z);

        // pool with weights e_c (scale by 1/Z after the reduction)
#pragma unroll
        for (int q = 0; q < 16; q++) {
            float s = e[0] * v[0][q];
#pragma unroll
            for (int c = 1; c < CPT; c++) s = fmaf(e[c], v[c][q], s);
            t[q] = s;
        }
        vec_reduce16(t, lane);
        pval = squash16(t[0] * rZ);

        if (it < 2) {
#pragma unroll
            for (int q = 0; q < 16; q++) {
                const float pq = __shfl_sync(FULL, pval, q);
#pragma unroll
                for (int c = 0; c < CPT; c++)
                    logit[c] = fmaf(v[c][q], pq, logit[c]);
            }
        }
    }

    // ---- output: lanes 0..15 hold p[0..15] ----
    if (lane < 16)
        out[(size_t)n * (CAP_B * PSIZE) + j * PSIZE + lane] = pval;
}

extern "C" void kernel_launch(void* const* d_in, const int* in_sizes, int n_in,
                              void* d_out, int out_size) {
    (void)in_sizes; (void)n_in; (void)out_size;
    const float* x = (const float*)d_in[0];
    const float* w = (const float*)d_in[1];
    float* out = (float*)d_out;

    // 1) single prep launch: fp32 -> fp16 (w transposed to j-major) + x
    convert_kernel<<<(W4 + X4 + 255) / 256, 256>>>(w, x);

    // 2) fused transform + routing, one warp per (n, j)
    dim3 grid(NPOS * CAP_B);   // 14400
    caps_warp_kernel<<<grid, 32>>>(out);
}

// round 17
// speedup vs baseline: 1.3632x; 1.0029x over previous
#include <cuda_runtime.h>
#include <cuda_fp16.h>

// Problem constants
#define CAP_A   32
#define CAP_B   32
#define KK      3
#define PSIZE   16
#define STRIDE  2
#define OH      15
#define OW      15
#define NBATCH  2
#define NPOS    (NBATCH*OH*OW)   // 450
#define KKA     (KK*KK*CAP_A)    // 288
#define NX      (NBATCH*32*32*512)  // 1,048,576 x elements
#define EPS_SQ  1e-8f
#define CPT     9                // capsules per thread (one warp per (n,j))
#define FULL    0xffffffffu
#define W4      (KKA*CAP_B*4)    // 36864 float4s in w
#define X4      (NX/4)           // 262144 float4s in x

// fp16 staging buffers, CHUNK-SPLIT layout: each logical 512-half block
// (one x pixel / one (j,c) weight group) stores chunk k (halves 8k..8k+7 of
// every lane) densely: offset = k*256 + lane*8 + m. Each warp LDG.128 then
// covers a dense 512B span -> 4 L1 wavefronts instead of 8.
__device__ __half w_h[CAP_B * KKA * PSIZE];   // blocks: (j*9 + c)
__device__ __half x_h[NX];                    // blocks: pixel index

// Single prep kernel: converts w (j-major transpose) and x to fp16,
// writing the chunk-split layout.
__global__ void convert_kernel(const float* __restrict__ w,
                               const float* __restrict__ x) {
    const int f = blockIdx.x * blockDim.x + threadIdx.x;
    if (f < W4) {
        const int q4 = f & 3;          // which float4 within the 16-vec
        const int j  = (f >> 2) & 31;
        const int i  = f >> 7;
        const int c  = i >> 5;         // i / 32
        const int a  = i & 31;         // lane
        const float4 val = reinterpret_cast<const float4*>(w)[f];
        // halves m = q4*4 .. q4*4+3 ; k = q4>>1 ; mm = (q4&1)*4
        __half* dstp = w_h + ((size_t)(j * 9 + c) * 512
                              + (q4 >> 1) * 256 + a * 8 + (q4 & 1) * 4);
        __half2* dst = reinterpret_cast<__half2*>(dstp);
        dst[0] = __floats2half2_rn(val.x, val.y);
        dst[1] = __floats2half2_rn(val.z, val.w);
    } else {
        const int g = f - W4;
        if (g < X4) {
            const int e   = g * 4;          // half index (4-aligned)
            const int blk = e >> 9;         // pixel block
            const int r   = e & 511;
            const int a   = r >> 4;         // lane
            const int m   = r & 15;         // half-within-lane (4-aligned)
            const float4 val = reinterpret_cast<const float4*>(x)[g];
            __half* dstp = x_h + ((size_t)blk * 512
                                  + (m >> 3) * 256 + a * 8 + (m & 7));
            __half2* dst = reinterpret_cast<__half2*>(dstp);
            dst[0] = __floats2half2_rn(val.x, val.y);
            dst[1] = __floats2half2_rn(val.z, val.w);
        }
    }
}

// Load this lane's 16 halves from a chunk-split 512-half block; widen to fp32.
// Both LDG.128s are dense 512B warp transactions (4 wavefronts each).
__device__ __forceinline__ void load16h_s(const __half* __restrict__ blk,
                                          int lane, float o[16]) {
    uint4 u0 = *reinterpret_cast<const uint4*>(blk + lane * 8);
    uint4 u1 = *reinterpret_cast<const uint4*>(blk + 256 + lane * 8);
    const unsigned wds[8] = {u0.x, u0.y, u0.z, u0.w, u1.x, u1.y, u1.z, u1.w};
#pragma unroll
    for (int k = 0; k < 8; k++) {
        const float2 f2 = __half22float2(*reinterpret_cast<const __half2*>(&wds[k]));
        o[2 * k]     = f2.x;
        o[2 * k + 1] = f2.y;
    }
}

// Butterfly vector-exchange reduction: 32 lanes each hold t[0..15];
// afterwards lane l holds the lane-sum of component (l & 15). 31 shuffles.
__device__ __forceinline__ void vec_reduce16(float t[16], int lane) {
#pragma unroll
    for (int k = 0; k < 16; k++)
        t[k] += __shfl_xor_sync(FULL, t[k], 16);
    {
        const bool hi = lane & 8;
#pragma unroll
        for (int k = 0; k < 8; k++) {
            float keep = hi ? t[k + 8] : t[k];
            float send = hi ? t[k]     : t[k + 8];
            t[k] = keep + __shfl_xor_sync(FULL, send, 8);
        }
    }
    {
        const bool hi = lane & 4;
#pragma unroll
        for (int k = 0; k < 4; k++) {
            float keep = hi ? t[k + 4] : t[k];
            float send = hi ? t[k]     : t[k + 4];
            t[k] = keep + __shfl_xor_sync(FULL, send, 4);
        }
    }
    {
        const bool hi = lane & 2;
#pragma unroll
        for (int k = 0; k < 2; k++) {
            float keep = hi ? t[k + 2] : t[k];
            float send = hi ? t[k]     : t[k + 2];
            t[k] = keep + __shfl_xor_sync(FULL, send, 2);
        }
    }
    {
        const bool hi = lane & 1;
        float keep = hi ? t[1] : t[0];
        float send = hi ? t[0] : t[1];
        t[0] = keep + __shfl_xor_sync(FULL, send, 1);
    }
}

// Squash on the duplicated 16-vector (lanes l and l+16 both hold comp l&15).
__device__ __forceinline__ float squash16(float s) {
    float n2 = s * s;
#pragma unroll
    for (int off = 8; off >= 1; off >>= 1)
        n2 += __shfl_xor_sync(FULL, n2, off);
    return s * (n2 / (1.f + n2) * rsqrtf(n2 + EPS_SQ));
}

__global__ __launch_bounds__(32, 12) void caps_warp_kernel(
    float* __restrict__ out)         // (2, 15, 15, 512)
{
    const int bid = blockIdx.x;
    const int j   = bid & 31;
    const int n   = bid >> 5;
    const int b   = n / (OH * OW);
    const int rem = n % (OH * OW);
    const int oy  = rem / OW;
    const int ox  = rem % OW;

    const int lane = threadIdx.x;    // = a (input capsule type)

    // Block bases: x pixel blocks and (j,c) weight blocks, 512 halves each.
    const __half* xpix0 = x_h + (size_t)((b * 32 + oy * STRIDE) * 32
                                         + ox * STRIDE) * 512;
    const __half* wj    = w_h + (size_t)(j * 9) * 512;

    float v[CPT][16];
#pragma unroll
    for (int c = 0; c < CPT; c++) {
        const int ky = c / 3, kx = c % 3;
        float xm[16], wm[16];
        load16h_s(xpix0 + (size_t)(ky * 32 + kx) * 512, lane, xm);
        load16h_s(wj + (size_t)c * 512,                 lane, wm);
#pragma unroll
        for (int p = 0; p < 4; p++)
#pragma unroll
            for (int q = 0; q < 4; q++) {
                float acc = 0.f;
#pragma unroll
                for (int r = 0; r < 4; r++)
                    acc = fmaf(xm[p * 4 + r], wm[r * 4 + q], acc);
                v[c][p * 4 + q] = acc;
            }
    }

    float logit[CPT];
#pragma unroll
    for (int c = 0; c < CPT; c++) logit[c] = 0.f;

    float t[16];
    float pval;   // component (lane&15) of current p

    // ---- iteration 0: logits all zero -> r = 1/288 exactly ----
#pragma unroll
    for (int q = 0; q < 16; q++) {
        float s = v[0][q];
#pragma unroll
        for (int c = 1; c < CPT; c++) s += v[c][q];
        t[q] = s;
    }
    vec_reduce16(t, lane);
    pval = squash16(t[0] * (1.0f / (float)KKA));

    // agreement: logit_c += v_c . p  (p broadcast via inline shuffles)
#pragma unroll
    for (int q = 0; q < 16; q++) {
        const float pq = __shfl_sync(FULL, pval, q);
#pragma unroll
        for (int c = 0; c < CPT; c++)
            logit[c] = fmaf(v[c][q], pq, logit[c]);
    }

    // ---- iterations 1..2 ----
    // Logits are bounded (|logit| <~ 20), so softmax without max-subtraction
    // is safe in fp32 and mathematically identical.
#pragma unroll
    for (int it = 1; it < 3; it++) {
        float e[CPT], z = 0.f;
#pragma unroll
        for (int c = 0; c < CPT; c++) { e[c] = __expf(logit[c]); z += e[c]; }
#pragma unroll
        for (int off = 16; off >= 1; off >>= 1)
            z += __shfl_xor_sync(FULL, z, off);
        const float rZ = __frcp_rn(z);

        // pool with weights e_c (scale by 1/Z after the reduction)
#pragma unroll
        for (int q = 0; q < 16; q++) {
            float s = e[0] * v[0][q];
#pragma unroll
            for (int c = 1; c < CPT; c++) s = fmaf(e[c], v[c][q], s);
            t[q] = s;
        }
        vec_reduce16(t, lane);
        pval = squash16(t[0] * rZ);

        if (it < 2) {
#pragma unroll
            for (int q = 0; q < 16; q++) {
                const float pq = __shfl_sync(FULL, pval, q);
#pragma unroll
                for (int c = 0; c < CPT; c++)
                    logit[c] = fmaf(v[c][q], pq, logit[c]);
            }
        }
    }

    // ---- output: lanes 0..15 hold p[0..15] ----
    if (lane < 16)
        out[(size_t)n * (CAP_B * PSIZE) + j * PSIZE + lane] = pval;
}

extern "C" void kernel_launch(void* const* d_in, const int* in_sizes, int n_in,
                              void* d_out, int out_size) {
    (void)in_sizes; (void)n_in; (void)out_size;
    const float* x = (const float*)d_in[0];
    const float* w = (const float*)d_in[1];
    float* out = (float*)d_out;

    // 1) single prep launch: fp32 -> fp16, chunk-split staging layout
    convert_kernel<<<(W4 + X4 + 255) / 256, 256>>>(w, x);

    // 2) fused transform + routing, one warp per (n, j)
    dim3 grid(NPOS * CAP_B);   // 14400
    caps_warp_kernel<<<grid, 32>>>(out);
}